// round 2
// baseline (speedup 1.0000x reference)
#include <cuda_runtime.h>
#include <cstdint>
#include <cstddef>

// ---------------- problem constants ----------------
#define LT    392          // tokens per window
#define CH    128          // channels
#define NH    4            // heads
#define HDIM  32           // head dim
#define NWIN  8            // number of distinct window masks
#define BATCH 512          // batch * windows
#define QK_SCALE 0.17677669529663687f   // 32^-0.5

// attention tiling
#define QT          28     // queries per CTA
#define ATT_THREADS 224    // 7 warps, warp -> 4 query rows
#define KT_PITCH    401    // padded pitch for transposed K (odd -> conflict free)
#define JSPLIT      4      // split of the 64-batch loop across CTAs (wave-quantization fix)
#define JCHUNK      (64 / JSPLIT)

// ---------------- scratch (static device globals; no runtime alloc) ----------------
__device__ float g_q[(size_t)BATCH * NH * LT * HDIM];
__device__ float g_k[(size_t)BATCH * NH * LT * HDIM];
__device__ float g_v[(size_t)BATCH * NH * LT * HDIM];
__device__ float g_comb[(size_t)NWIN * NH * LT * LT];   // mask + rel-pos bias, [nw][h][q][k]
__device__ float g_ao[(size_t)BATCH * LT * CH];         // attention output before proj

// ---------------- kernel 1: combined mask + relative position bias ----------------
// rel idx computed analytically: token n -> (z=n/49, y=(n/7)%7, x=n%7)
// idx = (dz+7)*169 + (dy+6)*13 + (dx+6)   (max 2534)
__global__ void comb_kernel(const float* __restrict__ mask,
                            const float* __restrict__ table) {
    int e = blockIdx.x * 256 + threadIdx.x;
    if (e >= NWIN * NH * LT * LT) return;
    int k = e % LT;
    int t = e / LT;
    int q = t % LT; t /= LT;
    int h = t % NH;
    int nw = t / NH;
    int zq = q / 49, yq = (q / 7) % 7, xq = q % 7;
    int zk = k / 49, yk = (k / 7) % 7, xk = k % 7;
    int idx = (zq - zk + 7) * 169 + (yq - yk + 6) * 13 + (xq - xk + 6);
    g_comb[e] = mask[((size_t)nw * LT + q) * LT + k] + table[idx * NH + h];
}

// ---------------- kernel 2/4: fp32 tiled GEMM, 128x128x16, 8x8 per thread ----------
// MODE 0: A = x [M,128], B = qkv_w [128,384]; scatter q(*SCALE)/k/v into [B,H,L,HD]
// MODE 1: A = g_ao [M,128], B = proj_w [128,128]; write final output
template<int N, int MODE>
__global__ __launch_bounds__(256) void gemm_kernel(const float* __restrict__ A,
                                                   const float* __restrict__ Bw,
                                                   const float* __restrict__ bias,
                                                   float* __restrict__ out) {
    __shared__ float As[16][128];   // [k][m] (transposed)
    __shared__ float Bs[16][128];   // [k][n]
    const float* Aeff = (MODE == 1) ? g_ao : A;

    int m0 = blockIdx.x * 128;
    int n0 = blockIdx.y * 128;
    int tid = threadIdx.x;
    int ty = tid >> 4, tx = tid & 15;

    float acc[8][8];
#pragma unroll
    for (int i = 0; i < 8; i++)
#pragma unroll
        for (int j = 0; j < 8; j++) acc[i][j] = 0.f;

    for (int k0 = 0; k0 < 128; k0 += 16) {
        // A tile: 128 rows x 16 cols, float4 loads, transposed stores
        int ar = tid >> 2;
        int ac = (tid & 3) << 2;
#pragma unroll
        for (int p = 0; p < 2; p++) {
            int row = ar + p * 64;
            float4 a = *(const float4*)&Aeff[(size_t)(m0 + row) * 128 + k0 + ac];
            As[ac + 0][row] = a.x; As[ac + 1][row] = a.y;
            As[ac + 2][row] = a.z; As[ac + 3][row] = a.w;
        }
        // B tile: 16 rows x 128 cols
        int br = tid >> 5;
        int bc = (tid & 31) << 2;
#pragma unroll
        for (int p = 0; p < 2; p++)
            *(float4*)&Bs[br + p * 8][bc] =
                *(const float4*)&Bw[(size_t)(k0 + br + p * 8) * N + n0 + bc];
        __syncthreads();

#pragma unroll
        for (int kk = 0; kk < 16; kk++) {
            float a8[8], b8[8];
            *(float4*)&a8[0] = *(const float4*)&As[kk][ty * 8];
            *(float4*)&a8[4] = *(const float4*)&As[kk][ty * 8 + 4];
            *(float4*)&b8[0] = *(const float4*)&Bs[kk][tx * 8];
            *(float4*)&b8[4] = *(const float4*)&Bs[kk][tx * 8 + 4];
#pragma unroll
            for (int i = 0; i < 8; i++)
#pragma unroll
                for (int j = 0; j < 8; j++)
                    acc[i][j] += a8[i] * b8[j];
        }
        __syncthreads();
    }

#pragma unroll
    for (int i = 0; i < 8; i++) {
        int m = m0 + ty * 8 + i;
#pragma unroll
        for (int j = 0; j < 8; j++) {
            int n = n0 + tx * 8 + j;
            float v = acc[i][j] + bias[n];
            if (MODE == 0) {
                int b = m / LT, l = m % LT;
                int which = n >> 7;           // 0=q 1=k 2=v
                int c = n & 127;
                int h = c >> 5, d = c & 31;
                size_t off = (((size_t)b * NH + h) * LT + l) * HDIM + d;
                if (which == 0)      g_q[off] = v * QK_SCALE;
                else if (which == 1) g_k[off] = v;
                else                 g_v[off] = v;
            } else {
                out[(size_t)m * CH + n] = v;
            }
        }
    }
}

// ---------------- kernel 3: fused attention --------------------------------------
// grid (14, 4, 8*JSPLIT) = (q-tile, head, window-mask x batch-chunk). Each CTA
// loads its combined mask+bias tile ONCE, then loops JCHUNK batches sharing it.
__global__ __launch_bounds__(ATT_THREADS, 1) void attn_kernel() {
    extern __shared__ float sm[];
    float* sComb = sm;                      // QT*LT        = 10976
    float* sS    = sComb + QT * LT;         // QT*LT        = 10976
    float* sKt   = sS + QT * LT;            // 32*KT_PITCH  = 12832 (K transposed, padded)
    float* sV    = sKt + 32 * KT_PITCH;     // LT*32        = 12544
    float* sQ    = sV + LT * HDIM;          // QT*32        = 896
    float* sInv  = sQ + QT * HDIM;          // QT

    int tid  = threadIdx.x;
    int lane = tid & 31;
    int warp = tid >> 5;
    int q0 = blockIdx.x * QT;
    int h  = blockIdx.y;
    int nw = blockIdx.z & (NWIN - 1);
    int js = blockIdx.z >> 3;               // batch-chunk index 0..JSPLIT-1

    // combined tile -> smem (once per CTA; reused for JCHUNK batches)
    {
        const float* cb = &g_comb[(((size_t)nw * NH + h) * LT + q0) * LT];
        for (int i = tid * 4; i < QT * LT; i += ATT_THREADS * 4)
            *(float4*)&sComb[i] = *(const float4*)&cb[i];
    }

    for (int j = js * JCHUNK; j < (js + 1) * JCHUNK; j++) {
        int b = j * NWIN + nw;          // attn.reshape(B/NW, NW, ...) => b = j*NW + nw
        __syncthreads();                // protect smem reuse from previous iteration

        size_t base = ((size_t)b * NH + h) * LT * HDIM;
        // K -> transposed smem [d][k]
        for (int i4 = tid; i4 < LT * HDIM / 4; i4 += ATT_THREADS) {
            int l = i4 >> 3;
            int d = (i4 & 7) << 2;
            float4 kv = *(const float4*)&g_k[base + (size_t)l * HDIM + d];
            sKt[(d + 0) * KT_PITCH + l] = kv.x;
            sKt[(d + 1) * KT_PITCH + l] = kv.y;
            sKt[(d + 2) * KT_PITCH + l] = kv.z;
            sKt[(d + 3) * KT_PITCH + l] = kv.w;
        }
        // V -> smem [k][d]
        for (int i = tid * 4; i < LT * HDIM; i += ATT_THREADS * 4)
            *(float4*)&sV[i] = *(const float4*)&g_v[base + i];
        // Q tile -> smem
        {
            const float* gq = &g_q[base + (size_t)q0 * HDIM];
            for (int i = tid * 4; i < QT * HDIM; i += ATT_THREADS * 4)
                *(float4*)&sQ[i] = *(const float4*)&gq[i];
        }
        __syncthreads();

        // ---- S = comb + Q K^T : warp owns 4 query rows, lane owns k-strip ----
        int qw = warp * 4;
        float acc[13][4];
#pragma unroll
        for (int kk = 0; kk < 13; kk++) {
            int k = lane + kk * 32;
#pragma unroll
            for (int r = 0; r < 4; r++)
                acc[kk][r] = (k < LT) ? sComb[(qw + r) * LT + k] : -1e30f;
        }
#pragma unroll 1
        for (int dc = 0; dc < HDIM; dc += 8) {
            float qr[4][8];
#pragma unroll
            for (int r = 0; r < 4; r++) {
                float4 a  = *(const float4*)&sQ[(qw + r) * HDIM + dc];
                float4 bq = *(const float4*)&sQ[(qw + r) * HDIM + dc + 4];
                qr[r][0] = a.x;  qr[r][1] = a.y;  qr[r][2] = a.z;  qr[r][3] = a.w;
                qr[r][4] = bq.x; qr[r][5] = bq.y; qr[r][6] = bq.z; qr[r][7] = bq.w;
            }
#pragma unroll
            for (int kk = 0; kk < 13; kk++) {
                int k = lane + kk * 32;
                if (k < LT) {
#pragma unroll
                    for (int dd = 0; dd < 8; dd++) {
                        float kt = sKt[(dc + dd) * KT_PITCH + k];
#pragma unroll
                        for (int r = 0; r < 4; r++)
                            acc[kk][r] += qr[r][dd] * kt;
                    }
                }
            }
        }

        // ---- softmax per row, straight from registers ----
#pragma unroll
        for (int r = 0; r < 4; r++) {
            float mx = -1e30f;
#pragma unroll
            for (int kk = 0; kk < 13; kk++) mx = fmaxf(mx, acc[kk][r]);
#pragma unroll
            for (int o = 16; o > 0; o >>= 1)
                mx = fmaxf(mx, __shfl_xor_sync(0xffffffffu, mx, o));
            float sum = 0.f;
#pragma unroll
            for (int kk = 0; kk < 13; kk++) {
                int k = lane + kk * 32;
                if (k < LT) {
                    float p = __expf(acc[kk][r] - mx);
                    sum += p;
                    sS[(qw + r) * LT + k] = p;
                }
            }
#pragma unroll
            for (int o = 16; o > 0; o >>= 1)
                sum += __shfl_xor_sync(0xffffffffu, sum, o);
            if (lane == 0) sInv[qw + r] = 1.f / sum;
        }
        __syncthreads();

        // ---- O = (P V) * inv_sum : thread owns (q, 4 d-channels) ----
        {
            int q  = tid >> 3;
            int d4 = (tid & 7) << 2;
            const float* Srow = &sS[q * LT];
            float ox = 0.f, oy = 0.f, oz = 0.f, ow = 0.f;
#pragma unroll 2
            for (int k = 0; k < LT; k += 4) {
                float4 p = *(const float4*)&Srow[k];
                const float* vp = &sV[(size_t)k * HDIM + d4];
                float4 v0 = *(const float4*)&vp[0];
                float4 v1 = *(const float4*)&vp[HDIM];
                float4 v2 = *(const float4*)&vp[2 * HDIM];
                float4 v3 = *(const float4*)&vp[3 * HDIM];
                ox += p.x * v0.x + p.y * v1.x + p.z * v2.x + p.w * v3.x;
                oy += p.x * v0.y + p.y * v1.y + p.z * v2.y + p.w * v3.y;
                oz += p.x * v0.z + p.y * v1.z + p.z * v2.z + p.w * v3.z;
                ow += p.x * v0.w + p.y * v1.w + p.z * v2.w + p.w * v3.w;
            }
            float inv = sInv[q];
            float4 o4 = make_float4(ox * inv, oy * inv, oz * inv, ow * inv);
            *(float4*)&g_ao[((size_t)b * LT + q0 + q) * CH + h * HDIM + d4] = o4;
        }
    }
}

// ---------------- launch ----------------------------------------------------------
extern "C" void kernel_launch(void* const* d_in, const int* in_sizes, int n_in,
                              void* d_out, int out_size) {
    const float* x      = (const float*)d_in[0];
    const float* mask   = (const float*)d_in[1];
    const float* qkv_w  = (const float*)d_in[2];
    const float* qkv_b  = (const float*)d_in[3];
    const float* proj_w = (const float*)d_in[4];
    const float* proj_b = (const float*)d_in[5];
    const float* table  = (const float*)d_in[6];
    float* out = (float*)d_out;

    constexpr int SMEM_FLOATS = QT * LT * 2 + 32 * KT_PITCH + LT * HDIM + QT * HDIM + QT;
    constexpr int SMEM_BYTES  = SMEM_FLOATS * 4;   // 193008

    cudaFuncSetAttribute(attn_kernel,
                         cudaFuncAttributeMaxDynamicSharedMemorySize, SMEM_BYTES);

    // 1. combined mask + bias  [8,4,392,392]
    comb_kernel<<<(NWIN * NH * LT * LT) / 256, 256>>>(mask, table);

    // 2. QKV projection + scatter (M=200704, N=384, K=128)
    gemm_kernel<384, 0><<<dim3(200704 / 128, 3), 256>>>(x, qkv_w, qkv_b, nullptr);

    // 3. fused attention (JSPLIT batch chunks to kill the wave-quantization tail)
    attn_kernel<<<dim3(LT / QT, NH, NWIN * JSPLIT), ATT_THREADS, SMEM_BYTES>>>();

    // 4. output projection (M=200704, N=128, K=128)
    gemm_kernel<128, 1><<<dim3(200704 / 128, 1), 256>>>(nullptr, proj_w, proj_b, out);
}

// round 6
// speedup vs baseline: 2.6637x; 2.6637x over previous
#include <cuda_runtime.h>
#include <cstdint>
#include <cstddef>

// ---------------- problem constants ----------------
#define LT    392          // tokens per window
#define LP    416          // padded keys: 13 * 32
#define CH    128          // channels
#define NH    4            // heads
#define HDIM  32           // head dim
#define NWIN  8            // number of distinct window masks
#define BATCH 512          // batch * windows
#define QK_SCALE 0.17677669529663687f   // 32^-0.5

// attention tiling (mma.sync tf32)
#define KBLK  32           // keys per block
#define NKB   13           // key blocks (13*32 = 416)
#define QTILE 64           // queries per CTA (4 warps x 16 rows)
#define PK    36           // smem pitch (floats) for K and P/Q tiles -> conflict-free frags
#define PVP   40           // smem pitch for V -> conflict-free B frags

// ---------------- scratch (static device globals; no runtime alloc) ----------------
__device__ float g_q[(size_t)BATCH * NH * LT * HDIM];
__device__ float g_k[(size_t)BATCH * NH * LT * HDIM];
__device__ float g_v[(size_t)BATCH * NH * LT * HDIM];
__device__ float g_comb[(size_t)NWIN * NH * LT * LP];   // mask+bias, cols>=LT = -1e30
__device__ float g_ao[(size_t)BATCH * LT * CH];         // attention output before proj

// ---------------- helpers ---------------------------------------------------------
__device__ __forceinline__ uint32_t f2tf32(float f) {
    uint32_t u;
    asm("cvt.rna.tf32.f32 %0, %1;" : "=r"(u) : "f"(f));
    return u;
}

// mma.sync m16n8k8 tf32: D = A*B + D  (A row-major 16x8, B col-major 8x8)
__device__ __forceinline__ void mma_tf32(float c[4], const uint32_t a[4], const uint32_t b[2]) {
    asm volatile("mma.sync.aligned.m16n8k8.row.col.f32.tf32.tf32.f32 "
                 "{%0,%1,%2,%3}, {%4,%5,%6,%7}, {%8,%9}, {%0,%1,%2,%3};"
                 : "+f"(c[0]), "+f"(c[1]), "+f"(c[2]), "+f"(c[3])
                 : "r"(a[0]), "r"(a[1]), "r"(a[2]), "r"(a[3]), "r"(b[0]), "r"(b[1]));
}

// ---------------- kernel 1: combined mask + relative position bias (padded) ------
__global__ void comb_kernel(const float* __restrict__ mask,
                            const float* __restrict__ table) {
    int e = blockIdx.x * 256 + threadIdx.x;
    if (e >= NWIN * NH * LT * LP) return;
    int k = e % LP;
    int t = e / LP;
    int q = t % LT; t /= LT;
    int h = t % NH;
    int nw = t / NH;
    float val = -1e30f;
    if (k < LT) {
        int zq = q / 49, yq = (q / 7) % 7, xq = q % 7;
        int zk = k / 49, yk = (k / 7) % 7, xk = k % 7;
        int idx = (zq - zk + 7) * 169 + (yq - yk + 6) * 13 + (xq - xk + 6);
        val = mask[((size_t)nw * LT + q) * LT + k] + table[idx * NH + h];
    }
    g_comb[e] = val;
}

// ---------------- kernel 2/4: fp32 tiled GEMM, 128x128x16, 8x8 per thread ----------
template<int N, int MODE>
__global__ __launch_bounds__(256) void gemm_kernel(const float* __restrict__ A,
                                                   const float* __restrict__ Bw,
                                                   const float* __restrict__ bias,
                                                   float* __restrict__ out) {
    __shared__ float As[16][128];
    __shared__ float Bs[16][128];
    const float* Aeff = (MODE == 1) ? g_ao : A;

    int m0 = blockIdx.x * 128;
    int n0 = blockIdx.y * 128;
    int tid = threadIdx.x;
    int ty = tid >> 4, tx = tid & 15;

    float acc[8][8];
#pragma unroll
    for (int i = 0; i < 8; i++)
#pragma unroll
        for (int j = 0; j < 8; j++) acc[i][j] = 0.f;

    for (int k0 = 0; k0 < 128; k0 += 16) {
        int ar = tid >> 2;
        int ac = (tid & 3) << 2;
#pragma unroll
        for (int p = 0; p < 2; p++) {
            int row = ar + p * 64;
            float4 a = *(const float4*)&Aeff[(size_t)(m0 + row) * 128 + k0 + ac];
            As[ac + 0][row] = a.x; As[ac + 1][row] = a.y;
            As[ac + 2][row] = a.z; As[ac + 3][row] = a.w;
        }
        int br = tid >> 5;
        int bc = (tid & 31) << 2;
#pragma unroll
        for (int p = 0; p < 2; p++)
            *(float4*)&Bs[br + p * 8][bc] =
                *(const float4*)&Bw[(size_t)(k0 + br + p * 8) * N + n0 + bc];
        __syncthreads();

#pragma unroll
        for (int kk = 0; kk < 16; kk++) {
            float a8[8], b8[8];
            *(float4*)&a8[0] = *(const float4*)&As[kk][ty * 8];
            *(float4*)&a8[4] = *(const float4*)&As[kk][ty * 8 + 4];
            *(float4*)&b8[0] = *(const float4*)&Bs[kk][tx * 8];
            *(float4*)&b8[4] = *(const float4*)&Bs[kk][tx * 8 + 4];
#pragma unroll
            for (int i = 0; i < 8; i++)
#pragma unroll
                for (int j = 0; j < 8; j++)
                    acc[i][j] += a8[i] * b8[j];
        }
        __syncthreads();
    }

#pragma unroll
    for (int i = 0; i < 8; i++) {
        int m = m0 + ty * 8 + i;
#pragma unroll
        for (int j = 0; j < 8; j++) {
            int n = n0 + tx * 8 + j;
            float v = acc[i][j] + bias[n];
            if (MODE == 0) {
                int b = m / LT, l = m % LT;
                int which = n >> 7;
                int c = n & 127;
                int h = c >> 5, d = c & 31;
                size_t off = (((size_t)b * NH + h) * LT + l) * HDIM + d;
                if (which == 0)      g_q[off] = v * QK_SCALE;
                else if (which == 1) g_k[off] = v;
                else                 g_v[off] = v;
            } else {
                out[(size_t)m * CH + n] = v;
            }
        }
    }
}

// ---------------- kernel 3: mma.sync tf32 fused attention -------------------------
// CTA = (q-tile of 64, head, batch); 4 warps, warp owns 16 query rows.
// Flash-style: stream 13 key-blocks of 32; no max pass (logits tiny, |s+c|<~30).
__global__ __launch_bounds__(128) void attn_mma_kernel() {
    __shared__ uint32_t sK[KBLK * PK];     // tf32 bits, [key][d], pitch 36
    __shared__ uint32_t sV[KBLK * PVP];    // tf32 bits, [key][d], pitch 40
    __shared__ uint32_t sP[QTILE * PK];    // P tile (also Q staging), [q][*], pitch 36

    int tid  = threadIdx.x;
    int lane = tid & 31;
    int warp = tid >> 5;
    int q0 = blockIdx.x * QTILE;
    int h  = blockIdx.y;
    int b  = blockIdx.z;
    int nw = b & (NWIN - 1);

    size_t base = ((size_t)b * NH + h) * LT * HDIM;

    // ---- stage Q tile into sP (tf32, zero-padded rows), build A_Q fragments ----
    for (int i = tid; i < QTILE * 8; i += 128) {
        int r = i >> 3, d4 = (i & 7) << 2;
        int q = q0 + r;
        uint4 st = make_uint4(0u, 0u, 0u, 0u);
        if (q < LT) {
            float4 v = *(const float4*)&g_q[base + (size_t)q * HDIM + d4];
            st.x = f2tf32(v.x); st.y = f2tf32(v.y); st.z = f2tf32(v.z); st.w = f2tf32(v.w);
        }
        *(uint4*)&sP[r * PK + d4] = st;
    }
    __syncthreads();

    uint32_t aq[4][4];
    int rw = warp * 16 + (lane >> 2);       // this thread's row (r0) within CTA tile
    int cq = lane & 3;
#pragma unroll
    for (int k8 = 0; k8 < 4; k8++) {
        int c = k8 * 8 + cq;
        aq[k8][0] = sP[rw * PK + c];
        aq[k8][1] = sP[(rw + 8) * PK + c];
        aq[k8][2] = sP[rw * PK + c + 4];
        aq[k8][3] = sP[(rw + 8) * PK + c + 4];
    }
    __syncwarp();

    // comb rows (clamped for padded q rows; results unused there)
    int qg0 = q0 + warp * 16 + (lane >> 2);
    int qc0 = qg0 < LT ? qg0 : LT - 1;
    int qc1 = qg0 + 8 < LT ? qg0 + 8 : LT - 1;
    const float* crow0 = &g_comb[(((size_t)nw * NH + h) * LT + qc0) * LP];
    const float* crow1 = &g_comb[(((size_t)nw * NH + h) * LT + qc1) * LP];

    float oacc[4][4];
#pragma unroll
    for (int i = 0; i < 4; i++)
#pragma unroll
        for (int j = 0; j < 4; j++) oacc[i][j] = 0.f;
    float sum0 = 0.f, sum1 = 0.f;

    for (int kb = 0; kb < NKB; kb++) {
        // ---- fill K/V blocks (tf32, zero-padded keys) ----
        for (int i = tid; i < KBLK * 8; i += 128) {
            int rk = i >> 3, d4 = (i & 7) << 2;
            int key = kb * KBLK + rk;
            uint4 ks = make_uint4(0u, 0u, 0u, 0u);
            uint4 vs = make_uint4(0u, 0u, 0u, 0u);
            if (key < LT) {
                float4 kv = *(const float4*)&g_k[base + (size_t)key * HDIM + d4];
                float4 vv = *(const float4*)&g_v[base + (size_t)key * HDIM + d4];
                ks.x = f2tf32(kv.x); ks.y = f2tf32(kv.y); ks.z = f2tf32(kv.z); ks.w = f2tf32(kv.w);
                vs.x = f2tf32(vv.x); vs.y = f2tf32(vv.y); vs.z = f2tf32(vv.z); vs.w = f2tf32(vv.w);
            }
            *(uint4*)&sK[rk * PK + d4] = ks;
            *(uint4*)&sV[rk * PVP + d4] = vs;
        }
        __syncthreads();

        // ---- S = Q K^T : 4 n8-blocks x 4 k8-steps ----
        float sacc[4][4];
#pragma unroll
        for (int i = 0; i < 4; i++)
#pragma unroll
            for (int j = 0; j < 4; j++) sacc[i][j] = 0.f;
#pragma unroll
        for (int k8 = 0; k8 < 4; k8++) {
#pragma unroll
            for (int n8 = 0; n8 < 4; n8++) {
                uint32_t bf[2];
                int krow = n8 * 8 + (lane >> 2);      // key index (n dim)
                int kcol = k8 * 8 + (lane & 3);       // d index (k dim)
                bf[0] = sK[krow * PK + kcol];
                bf[1] = sK[krow * PK + kcol + 4];
                mma_tf32(sacc[n8], aq[k8], bf);
            }
        }

        // ---- p = exp(s + comb), accumulate row sums, store P (tf32) to sP ----
#pragma unroll
        for (int n8 = 0; n8 < 4; n8++) {
            int col = kb * KBLK + n8 * 8 + 2 * (lane & 3);
            float2 c0 = *(const float2*)&crow0[col];
            float2 c1 = *(const float2*)&crow1[col];
            float p00 = __expf(sacc[n8][0] + c0.x);
            float p01 = __expf(sacc[n8][1] + c0.y);
            float p10 = __expf(sacc[n8][2] + c1.x);
            float p11 = __expf(sacc[n8][3] + c1.y);
            sum0 += p00 + p01;
            sum1 += p10 + p11;
            uint2 s0 = make_uint2(f2tf32(p00), f2tf32(p01));
            uint2 s1 = make_uint2(f2tf32(p10), f2tf32(p11));
            int pc = n8 * 8 + 2 * (lane & 3);
            *(uint2*)&sP[rw * PK + pc] = s0;
            *(uint2*)&sP[(rw + 8) * PK + pc] = s1;
        }
        __syncwarp();

        // ---- O += P V : A = P from sP, B = V from sV ----
#pragma unroll
        for (int k8 = 0; k8 < 4; k8++) {
            uint32_t ap[4];
            int c = k8 * 8 + cq;
            ap[0] = sP[rw * PK + c];
            ap[1] = sP[(rw + 8) * PK + c];
            ap[2] = sP[rw * PK + c + 4];
            ap[3] = sP[(rw + 8) * PK + c + 4];
#pragma unroll
            for (int n8 = 0; n8 < 4; n8++) {
                uint32_t bf[2];
                int vrow = k8 * 8 + (lane & 3);       // key (k dim)
                int vcol = n8 * 8 + (lane >> 2);      // d (n dim)
                bf[0] = sV[vrow * PVP + vcol];
                bf[1] = sV[(vrow + 4) * PVP + vcol];
                mma_tf32(oacc[n8], ap, bf);
            }
        }
        __syncthreads();
    }

    // ---- row-sum reduction across the 4 lanes sharing each row ----
    sum0 += __shfl_xor_sync(0xffffffffu, sum0, 1);
    sum0 += __shfl_xor_sync(0xffffffffu, sum0, 2);
    sum1 += __shfl_xor_sync(0xffffffffu, sum1, 1);
    sum1 += __shfl_xor_sync(0xffffffffu, sum1, 2);
    float inv0 = 1.f / sum0;
    float inv1 = 1.f / sum1;

    // ---- write O ----
#pragma unroll
    for (int n8 = 0; n8 < 4; n8++) {
        int d = h * HDIM + n8 * 8 + 2 * (lane & 3);
        if (qg0 < LT) {
            float2 o0 = make_float2(oacc[n8][0] * inv0, oacc[n8][1] * inv0);
            *(float2*)&g_ao[((size_t)b * LT + qg0) * CH + d] = o0;
        }
        if (qg0 + 8 < LT) {
            float2 o1 = make_float2(oacc[n8][2] * inv1, oacc[n8][3] * inv1);
            *(float2*)&g_ao[((size_t)b * LT + qg0 + 8) * CH + d] = o1;
        }
    }
}

// ---------------- launch ----------------------------------------------------------
extern "C" void kernel_launch(void* const* d_in, const int* in_sizes, int n_in,
                              void* d_out, int out_size) {
    const float* x      = (const float*)d_in[0];
    const float* mask   = (const float*)d_in[1];
    const float* qkv_w  = (const float*)d_in[2];
    const float* qkv_b  = (const float*)d_in[3];
    const float* proj_w = (const float*)d_in[4];
    const float* proj_b = (const float*)d_in[5];
    const float* table  = (const float*)d_in[6];
    float* out = (float*)d_out;

    // 1. combined mask + bias  [8,4,392,416] (padded cols = -1e30)
    comb_kernel<<<(NWIN * NH * LT * LP) / 256, 256>>>(mask, table);

    // 2. QKV projection + scatter (M=200704, N=384, K=128)
    gemm_kernel<384, 0><<<dim3(200704 / 128, 3), 256>>>(x, qkv_w, qkv_b, nullptr);

    // 3. tf32 mma.sync fused attention: (q-tile, head, batch)
    attn_mma_kernel<<<dim3(7, NH, BATCH), 128>>>();

    // 4. output projection (M=200704, N=128, K=128)
    gemm_kernel<128, 1><<<dim3(200704 / 128, 1), 256>>>(nullptr, proj_w, proj_b, out);
}

// round 7
// speedup vs baseline: 4.3191x; 1.6214x over previous
#include <cuda_runtime.h>
#include <cstdint>
#include <cstddef>

// ---------------- problem constants ----------------
#define LT    392          // tokens per window
#define LP    416          // padded keys: 13 * 32
#define CH    128          // channels
#define NH    4            // heads
#define HDIM  32           // head dim
#define NWIN  8            // number of distinct window masks
#define BATCH 512          // batch * windows
#define MTOT  200704       // BATCH * LT
#define QK_SCALE 0.17677669529663687f   // 32^-0.5

// attention tiling (mma.sync tf32)
#define KBLK  32
#define NKB   13
#define QTILE 64
#define PK    36
#define PVP   40

// GEMM tiling (mma.sync tf32)
#define GPA   36           // A smem pitch [m][k] -> conflict-free A frags
#define GPB   136          // B smem pitch [k][n] -> conflict-free B frags

// ---------------- scratch (static device globals; no runtime alloc) ----------------
__device__ float g_q[(size_t)BATCH * NH * LT * HDIM];
__device__ float g_k[(size_t)BATCH * NH * LT * HDIM];
__device__ float g_v[(size_t)BATCH * NH * LT * HDIM];
__device__ float g_comb[(size_t)NWIN * NH * LT * LP];   // mask+bias, cols>=LT = -1e30
__device__ float g_ao[(size_t)BATCH * LT * CH];         // attention output before proj

// ---------------- helpers ---------------------------------------------------------
__device__ __forceinline__ uint32_t f2tf32(float f) {
    uint32_t u;
    asm("cvt.rna.tf32.f32 %0, %1;" : "=r"(u) : "f"(f));
    return u;
}

// mma.sync m16n8k8 tf32: D = A*B + D  (A row-major 16x8, B col-major 8x8)
__device__ __forceinline__ void mma_tf32(float c[4], const uint32_t a[4], const uint32_t b[2]) {
    asm volatile("mma.sync.aligned.m16n8k8.row.col.f32.tf32.tf32.f32 "
                 "{%0,%1,%2,%3}, {%4,%5,%6,%7}, {%8,%9}, {%0,%1,%2,%3};"
                 : "+f"(c[0]), "+f"(c[1]), "+f"(c[2]), "+f"(c[3])
                 : "r"(a[0]), "r"(a[1]), "r"(a[2]), "r"(a[3]), "r"(b[0]), "r"(b[1]));
}

// ---------------- kernel 1: combined mask + relative position bias (padded) ------
__global__ void comb_kernel(const float* __restrict__ mask,
                            const float* __restrict__ table) {
    int e = blockIdx.x * 256 + threadIdx.x;
    if (e >= NWIN * NH * LT * LP) return;
    int k = e % LP;
    int t = e / LP;
    int q = t % LT; t /= LT;
    int h = t % NH;
    int nw = t / NH;
    float val = -1e30f;
    if (k < LT) {
        int zq = q / 49, yq = (q / 7) % 7, xq = q % 7;
        int zk = k / 49, yk = (k / 7) % 7, xk = k % 7;
        int idx = (zq - zk + 7) * 169 + (yq - yk + 6) * 13 + (xq - xk + 6);
        val = mask[((size_t)nw * LT + q) * LT + k] + table[idx * NH + h];
    }
    g_comb[e] = val;
}

// ---------------- kernel 2/4: tf32 mma.sync GEMM, 128x128 CTA tile ----------------
// 8 warps (2 x 4), warp tile 64x32. K=128, kblock=32.
// MODE 0: A = x, B = qkv_w [128,N=384]; scatter q(*SCALE)/k/v into [B,H,L,HD]
// MODE 1: A = g_ao, B = proj_w [128,128]; write final output + bias
template<int N, int MODE>
__global__ __launch_bounds__(256) void gemm_tc(const float* __restrict__ A,
                                               const float* __restrict__ Bw,
                                               const float* __restrict__ bias,
                                               float* __restrict__ out) {
    __shared__ uint32_t sA[128 * GPA];   // tf32 bits, [m][k]
    __shared__ uint32_t sB[32 * GPB];    // tf32 bits, [k][n]
    const float* Aeff = (MODE == 1) ? g_ao : A;

    int m0 = blockIdx.x * 128;
    int n0 = blockIdx.y * 128;
    int tid = threadIdx.x;
    int lane = tid & 31;
    int warp = tid >> 5;
    int warpM = warp & 1;                // 2 m-blocks of 64
    int warpN = warp >> 1;               // 4 n-blocks of 32

    float acc[4][4][4];
#pragma unroll
    for (int i = 0; i < 4; i++)
#pragma unroll
        for (int j = 0; j < 4; j++)
#pragma unroll
            for (int f = 0; f < 4; f++) acc[i][j][f] = 0.f;

    for (int k0 = 0; k0 < 128; k0 += 32) {
        // A tile: 128 rows x 32 cols -> sA[m][k], tf32
#pragma unroll
        for (int p = 0; p < 4; p++) {
            int idx = tid + p * 256;          // 0..1023
            int r = idx >> 3;                 // 8 float4 per row
            int c4 = (idx & 7) << 2;
            float4 a = *(const float4*)&Aeff[(size_t)(m0 + r) * 128 + k0 + c4];
            uint4 st = make_uint4(f2tf32(a.x), f2tf32(a.y), f2tf32(a.z), f2tf32(a.w));
            *(uint4*)&sA[r * GPA + c4] = st;
        }
        // B tile: 32 rows x 128 cols -> sB[k][n], tf32
#pragma unroll
        for (int p = 0; p < 4; p++) {
            int idx = tid + p * 256;
            int r = idx >> 5;                 // 32 float4 per row
            int c4 = (idx & 31) << 2;
            float4 b = *(const float4*)&Bw[(size_t)(k0 + r) * N + n0 + c4];
            uint4 st = make_uint4(f2tf32(b.x), f2tf32(b.y), f2tf32(b.z), f2tf32(b.w));
            *(uint4*)&sB[r * GPB + c4] = st;
        }
        __syncthreads();

#pragma unroll
        for (int k8 = 0; k8 < 4; k8++) {
            uint32_t af[4][4];
            int ar = warpM * 64 + (lane >> 2);
            int ac = k8 * 8 + (lane & 3);
#pragma unroll
            for (int i = 0; i < 4; i++) {
                af[i][0] = sA[(ar + i * 16) * GPA + ac];
                af[i][1] = sA[(ar + i * 16 + 8) * GPA + ac];
                af[i][2] = sA[(ar + i * 16) * GPA + ac + 4];
                af[i][3] = sA[(ar + i * 16 + 8) * GPA + ac + 4];
            }
            uint32_t bf[4][2];
            int bk = k8 * 8 + (lane & 3);
            int bn = warpN * 32 + (lane >> 2);
#pragma unroll
            for (int j = 0; j < 4; j++) {
                bf[j][0] = sB[bk * GPB + bn + j * 8];
                bf[j][1] = sB[(bk + 4) * GPB + bn + j * 8];
            }
#pragma unroll
            for (int i = 0; i < 4; i++)
#pragma unroll
                for (int j = 0; j < 4; j++)
                    mma_tf32(acc[i][j], af[i], bf[j]);
        }
        __syncthreads();
    }

    // ---- epilogue: C frag = (r,2c),(r,2c+1),(r+8,2c),(r+8,2c+1) ----
#pragma unroll
    for (int i = 0; i < 4; i++) {
        int r0 = m0 + warpM * 64 + i * 16 + (lane >> 2);
#pragma unroll
        for (int j = 0; j < 4; j++) {
            int c0 = n0 + warpN * 32 + j * 8 + 2 * (lane & 3);
            float b0 = bias[c0], b1 = bias[c0 + 1];
            float e00 = acc[i][j][0] + b0, e01 = acc[i][j][1] + b1;
            float e10 = acc[i][j][2] + b0, e11 = acc[i][j][3] + b1;
            if (MODE == 1) {
                *(float2*)&out[(size_t)r0 * CH + c0] = make_float2(e00, e01);
                *(float2*)&out[(size_t)(r0 + 8) * CH + c0] = make_float2(e10, e11);
            } else {
                int which = c0 >> 7;            // 0=q 1=k 2=v (block covers one 128-chunk)
                int cc = c0 & 127;
                int h = cc >> 5, d = cc & 31;
                float sc = (which == 0) ? QK_SCALE : 1.f;
                float* dstbuf = (which == 0) ? g_q : (which == 1) ? g_k : g_v;
#pragma unroll
                for (int rr = 0; rr < 2; rr++) {
                    int m = r0 + rr * 8;
                    int bb = m / LT, l = m % LT;
                    size_t off = (((size_t)bb * NH + h) * LT + l) * HDIM + d;
                    float v0 = (rr ? e10 : e00) * sc;
                    float v1 = (rr ? e11 : e01) * sc;
                    *(float2*)&dstbuf[off] = make_float2(v0, v1);
                }
            }
        }
    }
}

// ---------------- kernel 3: mma.sync tf32 fused attention -------------------------
__global__ __launch_bounds__(128) void attn_mma_kernel() {
    __shared__ uint32_t sK[KBLK * PK];     // tf32 bits, [key][d], pitch 36
    __shared__ uint32_t sV[KBLK * PVP];    // tf32 bits, [key][d], pitch 40
    __shared__ uint32_t sP[QTILE * PK];    // P tile (also Q staging), [q][*], pitch 36

    int tid  = threadIdx.x;
    int lane = tid & 31;
    int warp = tid >> 5;
    int q0 = blockIdx.x * QTILE;
    int h  = blockIdx.y;
    int b  = blockIdx.z;
    int nw = b & (NWIN - 1);

    size_t base = ((size_t)b * NH + h) * LT * HDIM;

    // ---- stage Q tile into sP (tf32, zero-padded rows), build A_Q fragments ----
    for (int i = tid; i < QTILE * 8; i += 128) {
        int r = i >> 3, d4 = (i & 7) << 2;
        int q = q0 + r;
        uint4 st = make_uint4(0u, 0u, 0u, 0u);
        if (q < LT) {
            float4 v = *(const float4*)&g_q[base + (size_t)q * HDIM + d4];
            st.x = f2tf32(v.x); st.y = f2tf32(v.y); st.z = f2tf32(v.z); st.w = f2tf32(v.w);
        }
        *(uint4*)&sP[r * PK + d4] = st;
    }
    __syncthreads();

    uint32_t aq[4][4];
    int rw = warp * 16 + (lane >> 2);
    int cq = lane & 3;
#pragma unroll
    for (int k8 = 0; k8 < 4; k8++) {
        int c = k8 * 8 + cq;
        aq[k8][0] = sP[rw * PK + c];
        aq[k8][1] = sP[(rw + 8) * PK + c];
        aq[k8][2] = sP[rw * PK + c + 4];
        aq[k8][3] = sP[(rw + 8) * PK + c + 4];
    }
    __syncwarp();

    int qg0 = q0 + warp * 16 + (lane >> 2);
    int qc0 = qg0 < LT ? qg0 : LT - 1;
    int qc1 = qg0 + 8 < LT ? qg0 + 8 : LT - 1;
    const float* crow0 = &g_comb[(((size_t)nw * NH + h) * LT + qc0) * LP];
    const float* crow1 = &g_comb[(((size_t)nw * NH + h) * LT + qc1) * LP];

    float oacc[4][4];
#pragma unroll
    for (int i = 0; i < 4; i++)
#pragma unroll
        for (int j = 0; j < 4; j++) oacc[i][j] = 0.f;
    float sum0 = 0.f, sum1 = 0.f;

    for (int kb = 0; kb < NKB; kb++) {
        for (int i = tid; i < KBLK * 8; i += 128) {
            int rk = i >> 3, d4 = (i & 7) << 2;
            int key = kb * KBLK + rk;
            uint4 ks = make_uint4(0u, 0u, 0u, 0u);
            uint4 vs = make_uint4(0u, 0u, 0u, 0u);
            if (key < LT) {
                float4 kv = *(const float4*)&g_k[base + (size_t)key * HDIM + d4];
                float4 vv = *(const float4*)&g_v[base + (size_t)key * HDIM + d4];
                ks.x = f2tf32(kv.x); ks.y = f2tf32(kv.y); ks.z = f2tf32(kv.z); ks.w = f2tf32(kv.w);
                vs.x = f2tf32(vv.x); vs.y = f2tf32(vv.y); vs.z = f2tf32(vv.z); vs.w = f2tf32(vv.w);
            }
            *(uint4*)&sK[rk * PK + d4] = ks;
            *(uint4*)&sV[rk * PVP + d4] = vs;
        }
        __syncthreads();

        float sacc[4][4];
#pragma unroll
        for (int i = 0; i < 4; i++)
#pragma unroll
            for (int j = 0; j < 4; j++) sacc[i][j] = 0.f;
#pragma unroll
        for (int k8 = 0; k8 < 4; k8++) {
#pragma unroll
            for (int n8 = 0; n8 < 4; n8++) {
                uint32_t bf[2];
                int krow = n8 * 8 + (lane >> 2);
                int kcol = k8 * 8 + (lane & 3);
                bf[0] = sK[krow * PK + kcol];
                bf[1] = sK[krow * PK + kcol + 4];
                mma_tf32(sacc[n8], aq[k8], bf);
            }
        }

#pragma unroll
        for (int n8 = 0; n8 < 4; n8++) {
            int col = kb * KBLK + n8 * 8 + 2 * (lane & 3);
            float2 c0 = *(const float2*)&crow0[col];
            float2 c1 = *(const float2*)&crow1[col];
            float p00 = __expf(sacc[n8][0] + c0.x);
            float p01 = __expf(sacc[n8][1] + c0.y);
            float p10 = __expf(sacc[n8][2] + c1.x);
            float p11 = __expf(sacc[n8][3] + c1.y);
            sum0 += p00 + p01;
            sum1 += p10 + p11;
            uint2 s0 = make_uint2(f2tf32(p00), f2tf32(p01));
            uint2 s1 = make_uint2(f2tf32(p10), f2tf32(p11));
            int pc = n8 * 8 + 2 * (lane & 3);
            *(uint2*)&sP[rw * PK + pc] = s0;
            *(uint2*)&sP[(rw + 8) * PK + pc] = s1;
        }
        __syncwarp();

#pragma unroll
        for (int k8 = 0; k8 < 4; k8++) {
            uint32_t ap[4];
            int c = k8 * 8 + cq;
            ap[0] = sP[rw * PK + c];
            ap[1] = sP[(rw + 8) * PK + c];
            ap[2] = sP[rw * PK + c + 4];
            ap[3] = sP[(rw + 8) * PK + c + 4];
#pragma unroll
            for (int n8 = 0; n8 < 4; n8++) {
                uint32_t bf[2];
                int vrow = k8 * 8 + (lane & 3);
                int vcol = n8 * 8 + (lane >> 2);
                bf[0] = sV[vrow * PVP + vcol];
                bf[1] = sV[(vrow + 4) * PVP + vcol];
                mma_tf32(oacc[n8], ap, bf);
            }
        }
        __syncthreads();
    }

    sum0 += __shfl_xor_sync(0xffffffffu, sum0, 1);
    sum0 += __shfl_xor_sync(0xffffffffu, sum0, 2);
    sum1 += __shfl_xor_sync(0xffffffffu, sum1, 1);
    sum1 += __shfl_xor_sync(0xffffffffu, sum1, 2);
    float inv0 = 1.f / sum0;
    float inv1 = 1.f / sum1;

#pragma unroll
    for (int n8 = 0; n8 < 4; n8++) {
        int d = h * HDIM + n8 * 8 + 2 * (lane & 3);
        if (qg0 < LT) {
            float2 o0 = make_float2(oacc[n8][0] * inv0, oacc[n8][1] * inv0);
            *(float2*)&g_ao[((size_t)b * LT + qg0) * CH + d] = o0;
        }
        if (qg0 + 8 < LT) {
            float2 o1 = make_float2(oacc[n8][2] * inv1, oacc[n8][3] * inv1);
            *(float2*)&g_ao[((size_t)b * LT + qg0 + 8) * CH + d] = o1;
        }
    }
}

// ---------------- launch ----------------------------------------------------------
extern "C" void kernel_launch(void* const* d_in, const int* in_sizes, int n_in,
                              void* d_out, int out_size) {
    const float* x      = (const float*)d_in[0];
    const float* mask   = (const float*)d_in[1];
    const float* qkv_w  = (const float*)d_in[2];
    const float* qkv_b  = (const float*)d_in[3];
    const float* proj_w = (const float*)d_in[4];
    const float* proj_b = (const float*)d_in[5];
    const float* table  = (const float*)d_in[6];
    float* out = (float*)d_out;

    // 1. combined mask + bias  [8,4,392,416] (padded cols = -1e30)
    comb_kernel<<<(NWIN * NH * LT * LP) / 256, 256>>>(mask, table);

    // 2. QKV projection + scatter (tf32 tensor cores; M=200704, N=384, K=128)
    gemm_tc<384, 0><<<dim3(MTOT / 128, 3), 256>>>(x, qkv_w, qkv_b, nullptr);

    // 3. tf32 mma.sync fused attention
    attn_mma_kernel<<<dim3(7, NH, BATCH), 128>>>();

    // 4. output projection (tf32 tensor cores; M=200704, N=128, K=128)
    gemm_tc<128, 1><<<dim3(MTOT / 128, 1), 256>>>(nullptr, proj_w, proj_b, out);
}